// round 2
// baseline (speedup 1.0000x reference)
#include <cuda_runtime.h>

#define BB 4
#define TT 2048
#define CC 1024
#define HS 64
#define KSPLIT 8
#define SCALE 0.03125f   // C^-0.5 = 1024^-0.5

// Scratch (static device allocations; no cudaMalloc allowed)
__device__ float g_q[BB * TT * HS];
__device__ float g_k[BB * TT * HS];
__device__ float g_v[BB * TT * HS];
__device__ float g_pacc[(size_t)BB * KSPLIT * TT * HS];
__device__ float g_pm[BB * KSPLIT * TT];
__device__ float g_pl[BB * KSPLIT * TT];

// ---------------------------------------------------------------------------
// Kernel 1: QKV projection.  X[8192,1024] @ W[1024,64] for Wq/Wk/Wv.
// grid = (64 row-tiles, 3), 128 threads.  BM=128, N=64, BK=32.
// 8x8 register micro-tile: 1 B LDS per FMA, A-loads broadcast -> FMA-bound.
// ---------------------------------------------------------------------------
__global__ __launch_bounds__(128) void qkv_kernel(
    const float* __restrict__ x,
    const float* __restrict__ Wq,
    const float* __restrict__ Wk,
    const float* __restrict__ Wv) {
    const float* W;
    float* out;
    if (blockIdx.y == 0)      { W = Wq; out = g_q; }
    else if (blockIdx.y == 1) { W = Wk; out = g_k; }
    else                      { W = Wv; out = g_v; }

    __shared__ float Xs[32][128];   // [k][row]  (transposed)
    __shared__ float Ws[32][64];    // [k][col]

    const int tid = threadIdx.x;
    const int tx = tid & 7;        // 8 col-groups of 8
    const int ty = tid >> 3;       // 16 row-groups of 8
    const int row0 = blockIdx.x * 128;

    const int l4r = tid >> 2;      // 0..31
    const int l4q = tid & 3;       // 0..3

    float acc[8][8] = {};

    for (int k0 = 0; k0 < CC; k0 += 32) {
        // X tile: 128 rows x 32 k, transposed into Xs.  Coalesced 64B/row-instr.
#pragma unroll
        for (int p = 0; p < 4; p++) {
#pragma unroll
            for (int i = 0; i < 2; i++) {
                int r = p * 32 + l4r;
                int f = l4q + 4 * i;
                float4 xv = *reinterpret_cast<const float4*>(
                    &x[(size_t)(row0 + r) * CC + k0 + f * 4]);
                Xs[f * 4 + 0][r] = xv.x;
                Xs[f * 4 + 1][r] = xv.y;
                Xs[f * 4 + 2][r] = xv.z;
                Xs[f * 4 + 3][r] = xv.w;
            }
        }
        // W tile: 32 x 64, row-major
#pragma unroll
        for (int i = 0; i < 4; i++) {
            int f = l4q + 4 * i;
            *reinterpret_cast<float4*>(&Ws[l4r][f * 4]) =
                *reinterpret_cast<const float4*>(&W[(size_t)(k0 + l4r) * HS + f * 4]);
        }
        __syncthreads();

#pragma unroll
        for (int kk = 0; kk < 32; kk++) {
            float4 a0 = *reinterpret_cast<float4*>(&Xs[kk][ty * 8]);
            float4 a1 = *reinterpret_cast<float4*>(&Xs[kk][ty * 8 + 4]);
            float4 b0 = *reinterpret_cast<float4*>(&Ws[kk][tx * 8]);
            float4 b1 = *reinterpret_cast<float4*>(&Ws[kk][tx * 8 + 4]);
            float av[8] = {a0.x, a0.y, a0.z, a0.w, a1.x, a1.y, a1.z, a1.w};
            float bv[8] = {b0.x, b0.y, b0.z, b0.w, b1.x, b1.y, b1.z, b1.w};
#pragma unroll
            for (int i = 0; i < 8; i++)
#pragma unroll
                for (int j = 0; j < 8; j++)
                    acc[i][j] += av[i] * bv[j];
        }
        __syncthreads();
    }

#pragma unroll
    for (int i = 0; i < 8; i++) {
        size_t r = (size_t)(row0 + ty * 8 + i) * HS + tx * 8;
        *reinterpret_cast<float4*>(&out[r]) =
            make_float4(acc[i][0], acc[i][1], acc[i][2], acc[i][3]);
        *reinterpret_cast<float4*>(&out[r + 4]) =
            make_float4(acc[i][4], acc[i][5], acc[i][6], acc[i][7]);
    }
}

// ---------------------------------------------------------------------------
// Kernel 2: flash-attention partials with key-split.
// grid = (32 q-tiles, KSPLIT, 4 batches), 128 threads.  BM=BN=64.
// Micro-tile: 8 q-rows (ty=tid>>4, 8 groups) x 4 keys/dims (tx=tid&15).
// Q/P reads broadcast across tx lanes; P stored natural (no transpose conflicts).
// ---------------------------------------------------------------------------
__global__ __launch_bounds__(128) void attn_partial_kernel() {
    const int qtile = blockIdx.x;
    const int split = blockIdx.y;
    const int b     = blockIdx.z;

    const int tid = threadIdx.x;
    const int tx = tid & 15;       // key/dim group (x4)
    const int ty = tid >> 4;       // row group (x8)

    __shared__ float Qt[64][64];   // [h][r], pre-scaled
    __shared__ float KP[64][64];   // K: [h][j]; reused as P: [r][j]
    __shared__ float Vs[64][64];   // [j][d]

    const int q0 = qtile * 64;
    const int lrow = tid >> 1;     // 0..63
    const int lh   = tid & 1;      // 0..1

    // Load Q tile, transposed + pre-scaled (2 threads/row, interleaved f4 slots)
#pragma unroll
    for (int i = 0; i < 8; i++) {
        int f = lh + 2 * i;
        float4 qv = *reinterpret_cast<const float4*>(
            &g_q[(size_t)(b * TT + q0 + lrow) * HS + f * 4]);
        Qt[f * 4 + 0][lrow] = qv.x * SCALE;
        Qt[f * 4 + 1][lrow] = qv.y * SCALE;
        Qt[f * 4 + 2][lrow] = qv.z * SCALE;
        Qt[f * 4 + 3][lrow] = qv.w * SCALE;
    }

    float m_[8], l_[8], acc[8][4];
#pragma unroll
    for (int i = 0; i < 8; i++) {
        m_[i] = -1e30f;
        l_[i] = 0.f;
#pragma unroll
        for (int d = 0; d < 4; d++) acc[i][d] = 0.f;
    }

    for (int kt = split; kt <= qtile; kt += KSPLIT) {
        const int k0 = kt * 64;
        __syncthreads();   // prior tile's P/V reads done (also covers Qt stores)

        // Load K (transposed) and V (natural)
#pragma unroll
        for (int i = 0; i < 8; i++) {
            int f = lh + 2 * i;
            float4 kv = *reinterpret_cast<const float4*>(
                &g_k[(size_t)(b * TT + k0 + lrow) * HS + f * 4]);
            KP[f * 4 + 0][lrow] = kv.x;
            KP[f * 4 + 1][lrow] = kv.y;
            KP[f * 4 + 2][lrow] = kv.z;
            KP[f * 4 + 3][lrow] = kv.w;
            *reinterpret_cast<float4*>(&Vs[lrow][f * 4]) =
                *reinterpret_cast<const float4*>(
                    &g_v[(size_t)(b * TT + k0 + lrow) * HS + f * 4]);
        }
        __syncthreads();

        // S = (Q*scale) K^T : 8 rows x 4 keys per thread
        float s[8][4] = {};
#pragma unroll 16
        for (int h = 0; h < 64; h++) {
            float4 a0 = *reinterpret_cast<float4*>(&Qt[h][ty * 8]);
            float4 a1 = *reinterpret_cast<float4*>(&Qt[h][ty * 8 + 4]);
            float4 bb = *reinterpret_cast<float4*>(&KP[h][tx * 4]);
            float av[8] = {a0.x, a0.y, a0.z, a0.w, a1.x, a1.y, a1.z, a1.w};
            float bv[4] = {bb.x, bb.y, bb.z, bb.w};
#pragma unroll
            for (int i = 0; i < 8; i++)
#pragma unroll
                for (int j = 0; j < 4; j++)
                    s[i][j] += av[i] * bv[j];
        }

        // Causal mask only on the diagonal tile
        if (kt == qtile) {
#pragma unroll
            for (int i = 0; i < 8; i++)
#pragma unroll
                for (int j = 0; j < 4; j++)
                    if (tx * 4 + j > ty * 8 + i) s[i][j] = -1e30f;
        }

        // Online softmax per row (reduce across the 16 tx lanes, same warp)
#pragma unroll
        for (int i = 0; i < 8; i++) {
            float tm = fmaxf(fmaxf(s[i][0], s[i][1]), fmaxf(s[i][2], s[i][3]));
#pragma unroll
            for (int o = 1; o < 16; o <<= 1)
                tm = fmaxf(tm, __shfl_xor_sync(0xffffffffu, tm, o));
            float nm  = fmaxf(m_[i], tm);
            float cor = __expf(m_[i] - nm);
            float rs = 0.f;
#pragma unroll
            for (int j = 0; j < 4; j++) {
                s[i][j] = __expf(s[i][j] - nm);
                rs += s[i][j];
            }
#pragma unroll
            for (int o = 1; o < 16; o <<= 1)
                rs += __shfl_xor_sync(0xffffffffu, rs, o);
            l_[i] = l_[i] * cor + rs;
            m_[i] = nm;
#pragma unroll
            for (int d = 0; d < 4; d++) acc[i][d] *= cor;
        }

        __syncthreads();   // done reading K from KP
        // Store P natural: KP[row][j]  (only 2-way bank conflict)
#pragma unroll
        for (int i = 0; i < 8; i++) {
            *reinterpret_cast<float4*>(&KP[ty * 8 + i][tx * 4]) =
                make_float4(s[i][0], s[i][1], s[i][2], s[i][3]);
        }
        __syncthreads();

        // acc += P V.  P reads broadcast across tx; V reads 2-way conflict.
#pragma unroll
        for (int j4 = 0; j4 < 16; j4++) {
            float4 v0 = *reinterpret_cast<float4*>(&Vs[j4 * 4 + 0][tx * 4]);
            float4 v1 = *reinterpret_cast<float4*>(&Vs[j4 * 4 + 1][tx * 4]);
            float4 v2 = *reinterpret_cast<float4*>(&Vs[j4 * 4 + 2][tx * 4]);
            float4 v3 = *reinterpret_cast<float4*>(&Vs[j4 * 4 + 3][tx * 4]);
#pragma unroll
            for (int i = 0; i < 8; i++) {
                float4 p = *reinterpret_cast<float4*>(&KP[ty * 8 + i][j4 * 4]);
                acc[i][0] += p.x * v0.x + p.y * v1.x + p.z * v2.x + p.w * v3.x;
                acc[i][1] += p.x * v0.y + p.y * v1.y + p.z * v2.y + p.w * v3.y;
                acc[i][2] += p.x * v0.z + p.y * v1.z + p.z * v2.z + p.w * v3.z;
                acc[i][3] += p.x * v0.w + p.y * v1.w + p.z * v2.w + p.w * v3.w;
            }
        }
    }

    // Write split partials (unnormalized acc + per-row m, l).
    const size_t base = (size_t)(b * KSPLIT + split) * TT + q0;
#pragma unroll
    for (int i = 0; i < 8; i++) {
        int r = ty * 8 + i;
        *reinterpret_cast<float4*>(&g_pacc[(base + r) * HS + tx * 4]) =
            make_float4(acc[i][0], acc[i][1], acc[i][2], acc[i][3]);
        if (tx == 0) {
            g_pm[base + r] = m_[i];
            g_pl[base + r] = l_[i];
        }
    }
}

// ---------------------------------------------------------------------------
// Kernel 3: combine split partials into the final output.
// ---------------------------------------------------------------------------
__global__ __launch_bounds__(256) void combine_kernel(float* __restrict__ out) {
    const int idx = blockIdx.x * 256 + threadIdx.x;  // 0 .. B*T*HS-1
    const int d   = idx & (HS - 1);
    const int row = idx >> 6;          // b*T + q
    const int b   = row >> 11;         // / 2048
    const int q   = row & (TT - 1);

    float M = -1e30f;
#pragma unroll
    for (int s = 0; s < KSPLIT; s++)
        M = fmaxf(M, g_pm[(size_t)(b * KSPLIT + s) * TT + q]);

    float L = 0.f, A = 0.f;
#pragma unroll
    for (int s = 0; s < KSPLIT; s++) {
        size_t pb = (size_t)(b * KSPLIT + s) * TT + q;
        float w = __expf(g_pm[pb] - M);
        L += g_pl[pb] * w;
        A += g_pacc[pb * HS + d] * w;
    }
    out[idx] = A / L;
}

// ---------------------------------------------------------------------------
extern "C" void kernel_launch(void* const* d_in, const int* in_sizes, int n_in,
                              void* d_out, int out_size) {
    const float* x  = (const float*)d_in[0];
    const float* Wq = (const float*)d_in[1];
    const float* Wk = (const float*)d_in[2];
    const float* Wv = (const float*)d_in[3];
    float* out = (float*)d_out;

    qkv_kernel<<<dim3((BB * TT) / 128, 3), 128>>>(x, Wq, Wk, Wv);
    attn_partial_kernel<<<dim3(TT / 64, KSPLIT, BB), 128>>>();
    combine_kernel<<<(BB * TT * HS) / 256, 256>>>(out);
}

// round 3
// speedup vs baseline: 1.1699x; 1.1699x over previous
#include <cuda_runtime.h>

#define BB 4
#define TT 2048
#define CC 1024
#define HS 64
#define KSPLIT 8
#define SCALE 0.03125f   // C^-0.5 = 1024^-0.5

typedef unsigned long long u64;

// ---- packed f32x2 helpers (sm_100+ PTX) -----------------------------------
__device__ __forceinline__ u64 pk2(float lo, float hi) {
    u64 r; asm("mov.b64 %0,{%1,%2};" : "=l"(r) : "f"(lo), "f"(hi)); return r;
}
__device__ __forceinline__ u64 pk1(float x) {
    u64 r; asm("mov.b64 %0,{%1,%1};" : "=l"(r) : "f"(x)); return r;
}
__device__ __forceinline__ void fma2(u64& d, u64 a, u64 b) {
    asm("fma.rn.f32x2 %0,%1,%2,%0;" : "+l"(d) : "l"(a), "l"(b));
}
__device__ __forceinline__ void mul2(u64& d, u64 a) {
    asm("mul.rn.f32x2 %0,%0,%1;" : "+l"(d) : "l"(a));
}
__device__ __forceinline__ void upk(u64 v, float& lo, float& hi) {
    asm("mov.b64 {%0,%1},%2;" : "=f"(lo), "=f"(hi) : "l"(v));
}

// Scratch (static device allocations; no cudaMalloc allowed)
__device__ float g_q[BB * TT * HS];
__device__ float g_k[BB * TT * HS];
__device__ float g_v[BB * TT * HS];
__device__ float g_pacc[(size_t)BB * KSPLIT * TT * HS];
__device__ float g_pm[BB * KSPLIT * TT];
__device__ float g_pl[BB * KSPLIT * TT];

// ---------------------------------------------------------------------------
// Kernel 1: QKV projection.  X[8192,1024] @ W[1024,64] for Wq/Wk/Wv.
// grid = (128 row-tiles, 3), 256 threads.  BM=64, BN=64, BK=32.
// 4x4 micro-tile, accumulators as f32x2 pairs -> FFMA2.
// ---------------------------------------------------------------------------
__global__ __launch_bounds__(256) void qkv_kernel(
    const float* __restrict__ x,
    const float* __restrict__ Wq,
    const float* __restrict__ Wk,
    const float* __restrict__ Wv) {
    const float* W;
    float* out;
    if (blockIdx.y == 0)      { W = Wq; out = g_q; }
    else if (blockIdx.y == 1) { W = Wk; out = g_k; }
    else                      { W = Wv; out = g_v; }

    __shared__ float Xs[32][64];   // [k][row]  (transposed)
    __shared__ float Ws[32][64];   // [k][col]

    const int tid = threadIdx.x;
    const int tx = tid & 15;       // 16 col groups of 4
    const int ty = tid >> 4;       // 16 row groups of 4
    const int row0 = blockIdx.x * 64;

    const int lrow = tid >> 2;     // 0..63
    const int lq   = tid & 3;      // 0..3
    const int wk   = tid >> 3;     // 0..31
    const int wf   = tid & 7;      // 0..7

    u64 acc[4][2] = {};            // 4 rows x (2 f32x2 = 4 cols)

    for (int k0 = 0; k0 < CC; k0 += 32) {
        // X tile 64x32, transposed into smem
#pragma unroll
        for (int p = 0; p < 2; p++) {
            int f = lq + p * 4;
            float4 xv = *reinterpret_cast<const float4*>(
                &x[(size_t)(row0 + lrow) * CC + k0 + f * 4]);
            Xs[f * 4 + 0][lrow] = xv.x;
            Xs[f * 4 + 1][lrow] = xv.y;
            Xs[f * 4 + 2][lrow] = xv.z;
            Xs[f * 4 + 3][lrow] = xv.w;
        }
        // W tile 32x64, row-major
#pragma unroll
        for (int p = 0; p < 2; p++) {
            int f = wf + p * 8;
            *reinterpret_cast<float4*>(&Ws[wk][f * 4]) =
                *reinterpret_cast<const float4*>(&W[(size_t)(k0 + wk) * HS + f * 4]);
        }
        __syncthreads();

#pragma unroll
        for (int kk = 0; kk < 32; kk++) {
            float4 a = *reinterpret_cast<float4*>(&Xs[kk][ty * 4]);
            float4 b = *reinterpret_cast<float4*>(&Ws[kk][tx * 4]);
            u64 b01 = pk2(b.x, b.y);
            u64 b23 = pk2(b.z, b.w);
            float av[4] = {a.x, a.y, a.z, a.w};
#pragma unroll
            for (int i = 0; i < 4; i++) {
                u64 ai = pk1(av[i]);
                fma2(acc[i][0], ai, b01);
                fma2(acc[i][1], ai, b23);
            }
        }
        __syncthreads();
    }

#pragma unroll
    for (int i = 0; i < 4; i++) {
        *reinterpret_cast<ulonglong2*>(
            &out[(size_t)(row0 + ty * 4 + i) * HS + tx * 4]) =
            make_ulonglong2(acc[i][0], acc[i][1]);
    }
}

// ---------------------------------------------------------------------------
// Kernel 2: flash-attention partials with key-split (FFMA2 GEMM loops).
// grid = (32 q-tiles, KSPLIT, 4 batches), 128 threads.  BM=BN=64.
// Micro-tile: 8 q-rows (ty) x 4 keys/dims (tx).
// ---------------------------------------------------------------------------
__global__ __launch_bounds__(128) void attn_partial_kernel() {
    const int qtile = blockIdx.x;
    const int split = blockIdx.y;
    const int b     = blockIdx.z;

    const int tid = threadIdx.x;
    const int tx = tid & 15;       // key/dim group (x4)
    const int ty = tid >> 4;       // row group (x8)

    __shared__ float Qt[64][64];   // [h][r], pre-scaled
    __shared__ float KP[64][64];   // K: [h][j]; reused as P: [r][j]
    __shared__ float Vs[64][64];   // [j][d]

    const int q0 = qtile * 64;
    const int lrow = tid >> 1;     // 0..63
    const int lh   = tid & 1;      // 0..1

    // Load Q tile, transposed + pre-scaled
#pragma unroll
    for (int i = 0; i < 8; i++) {
        int f = lh + 2 * i;
        float4 qv = *reinterpret_cast<const float4*>(
            &g_q[(size_t)(b * TT + q0 + lrow) * HS + f * 4]);
        Qt[f * 4 + 0][lrow] = qv.x * SCALE;
        Qt[f * 4 + 1][lrow] = qv.y * SCALE;
        Qt[f * 4 + 2][lrow] = qv.z * SCALE;
        Qt[f * 4 + 3][lrow] = qv.w * SCALE;
    }

    float m_[8], l_[8];
    u64 acc[8][2] = {};            // 8 rows x (2 f32x2 = 4 dims)
#pragma unroll
    for (int i = 0; i < 8; i++) { m_[i] = -1e30f; l_[i] = 0.f; }

    for (int kt = split; kt <= qtile; kt += KSPLIT) {
        const int k0 = kt * 64;
        __syncthreads();   // prior tile's P/V reads done (covers Qt stores too)

        // Load K (transposed) and V (natural)
#pragma unroll
        for (int i = 0; i < 8; i++) {
            int f = lh + 2 * i;
            float4 kv = *reinterpret_cast<const float4*>(
                &g_k[(size_t)(b * TT + k0 + lrow) * HS + f * 4]);
            KP[f * 4 + 0][lrow] = kv.x;
            KP[f * 4 + 1][lrow] = kv.y;
            KP[f * 4 + 2][lrow] = kv.z;
            KP[f * 4 + 3][lrow] = kv.w;
            *reinterpret_cast<float4*>(&Vs[lrow][f * 4]) =
                *reinterpret_cast<const float4*>(
                    &g_v[(size_t)(b * TT + k0 + lrow) * HS + f * 4]);
        }
        __syncthreads();

        // S = (Q*scale) K^T : 8 rows x 4 keys per thread, f32x2 pairs over keys
        u64 sp[8][2] = {};
#pragma unroll 16
        for (int h = 0; h < 64; h++) {
            float4 a0 = *reinterpret_cast<float4*>(&Qt[h][ty * 8]);
            float4 a1 = *reinterpret_cast<float4*>(&Qt[h][ty * 8 + 4]);
            float4 bb = *reinterpret_cast<float4*>(&KP[h][tx * 4]);
            u64 b01 = pk2(bb.x, bb.y);
            u64 b23 = pk2(bb.z, bb.w);
            float av[8] = {a0.x, a0.y, a0.z, a0.w, a1.x, a1.y, a1.z, a1.w};
#pragma unroll
            for (int i = 0; i < 8; i++) {
                u64 ai = pk1(av[i]);
                fma2(sp[i][0], ai, b01);
                fma2(sp[i][1], ai, b23);
            }
        }

        // Unpack scores once per tile
        float s[8][4];
#pragma unroll
        for (int i = 0; i < 8; i++) {
            upk(sp[i][0], s[i][0], s[i][1]);
            upk(sp[i][1], s[i][2], s[i][3]);
        }

        // Causal mask only on the diagonal tile
        if (kt == qtile) {
#pragma unroll
            for (int i = 0; i < 8; i++)
#pragma unroll
                for (int j = 0; j < 4; j++)
                    if (tx * 4 + j > ty * 8 + i) s[i][j] = -1e30f;
        }

        // Online softmax per row (reduce across the 16 tx lanes, same warp)
#pragma unroll
        for (int i = 0; i < 8; i++) {
            float tm = fmaxf(fmaxf(s[i][0], s[i][1]), fmaxf(s[i][2], s[i][3]));
#pragma unroll
            for (int o = 1; o < 16; o <<= 1)
                tm = fmaxf(tm, __shfl_xor_sync(0xffffffffu, tm, o));
            float nm  = fmaxf(m_[i], tm);
            float cor = __expf(m_[i] - nm);
            float rs = 0.f;
#pragma unroll
            for (int j = 0; j < 4; j++) {
                s[i][j] = __expf(s[i][j] - nm);
                rs += s[i][j];
            }
#pragma unroll
            for (int o = 1; o < 16; o <<= 1)
                rs += __shfl_xor_sync(0xffffffffu, rs, o);
            l_[i] = l_[i] * cor + rs;
            m_[i] = nm;
            u64 corp = pk1(cor);
            mul2(acc[i][0], corp);
            mul2(acc[i][1], corp);
        }

        __syncthreads();   // done reading K from KP
        // Store P natural: KP[row][j]
#pragma unroll
        for (int i = 0; i < 8; i++) {
            *reinterpret_cast<float4*>(&KP[ty * 8 + i][tx * 4]) =
                make_float4(s[i][0], s[i][1], s[i][2], s[i][3]);
        }
        __syncthreads();

        // acc += P V  (f32x2 pairs over dims)
#pragma unroll
        for (int j4 = 0; j4 < 16; j4++) {
            float4 v0 = *reinterpret_cast<float4*>(&Vs[j4 * 4 + 0][tx * 4]);
            float4 v1 = *reinterpret_cast<float4*>(&Vs[j4 * 4 + 1][tx * 4]);
            float4 v2 = *reinterpret_cast<float4*>(&Vs[j4 * 4 + 2][tx * 4]);
            float4 v3 = *reinterpret_cast<float4*>(&Vs[j4 * 4 + 3][tx * 4]);
            u64 v0a = pk2(v0.x, v0.y), v0b = pk2(v0.z, v0.w);
            u64 v1a = pk2(v1.x, v1.y), v1b = pk2(v1.z, v1.w);
            u64 v2a = pk2(v2.x, v2.y), v2b = pk2(v2.z, v2.w);
            u64 v3a = pk2(v3.x, v3.y), v3b = pk2(v3.z, v3.w);
#pragma unroll
            for (int i = 0; i < 8; i++) {
                float4 p = *reinterpret_cast<float4*>(&KP[ty * 8 + i][j4 * 4]);
                u64 px = pk1(p.x), py = pk1(p.y), pz = pk1(p.z), pw = pk1(p.w);
                fma2(acc[i][0], px, v0a); fma2(acc[i][1], px, v0b);
                fma2(acc[i][0], py, v1a); fma2(acc[i][1], py, v1b);
                fma2(acc[i][0], pz, v2a); fma2(acc[i][1], pz, v2b);
                fma2(acc[i][0], pw, v3a); fma2(acc[i][1], pw, v3b);
            }
        }
    }

    // Write split partials (unnormalized acc + per-row m, l).
    const size_t base = (size_t)(b * KSPLIT + split) * TT + q0;
#pragma unroll
    for (int i = 0; i < 8; i++) {
        int r = ty * 8 + i;
        *reinterpret_cast<ulonglong2*>(&g_pacc[(base + r) * HS + tx * 4]) =
            make_ulonglong2(acc[i][0], acc[i][1]);
        if (tx == 0) {
            g_pm[base + r] = m_[i];
            g_pl[base + r] = l_[i];
        }
    }
}

// ---------------------------------------------------------------------------
// Kernel 3: combine split partials into the final output.
// ---------------------------------------------------------------------------
__global__ __launch_bounds__(256) void combine_kernel(float* __restrict__ out) {
    const int idx = blockIdx.x * 256 + threadIdx.x;  // 0 .. B*T*HS-1
    const int d   = idx & (HS - 1);
    const int row = idx >> 6;          // b*T + q
    const int b   = row >> 11;         // / 2048
    const int q   = row & (TT - 1);

    float M = -1e30f;
#pragma unroll
    for (int s = 0; s < KSPLIT; s++)
        M = fmaxf(M, g_pm[(size_t)(b * KSPLIT + s) * TT + q]);

    float L = 0.f, A = 0.f;
#pragma unroll
    for (int s = 0; s < KSPLIT; s++) {
        size_t pb = (size_t)(b * KSPLIT + s) * TT + q;
        float w = __expf(g_pm[pb] - M);
        L += g_pl[pb] * w;
        A += g_pacc[pb * HS + d] * w;
    }
    out[idx] = A / L;
}

// ---------------------------------------------------------------------------
extern "C" void kernel_launch(void* const* d_in, const int* in_sizes, int n_in,
                              void* d_out, int out_size) {
    const float* x  = (const float*)d_in[0];
    const float* Wq = (const float*)d_in[1];
    const float* Wk = (const float*)d_in[2];
    const float* Wv = (const float*)d_in[3];
    float* out = (float*)d_out;

    qkv_kernel<<<dim3((BB * TT) / 64, 3), 256>>>(x, Wq, Wk, Wv);
    attn_partial_kernel<<<dim3(TT / 64, KSPLIT, BB), 128>>>();
    combine_kernel<<<(BB * TT * HS) / 256, 256>>>(out);
}

// round 5
// speedup vs baseline: 1.1970x; 1.0231x over previous
#include <cuda_runtime.h>

#define BB 4
#define TT 2048
#define CC 1024
#define HS 64
#define KSPLIT 8
#define SCALE 0.03125f   // C^-0.5 = 1024^-0.5

typedef unsigned long long u64;

// ---- packed f32x2 helpers (sm_100+ PTX) -----------------------------------
__device__ __forceinline__ u64 pk2(float lo, float hi) {
    u64 r; asm("mov.b64 %0,{%1,%2};" : "=l"(r) : "f"(lo), "f"(hi)); return r;
}
__device__ __forceinline__ u64 pk1(float x) {
    u64 r; asm("mov.b64 %0,{%1,%1};" : "=l"(r) : "f"(x)); return r;
}
__device__ __forceinline__ void fma2(u64& d, u64 a, u64 b) {
    asm("fma.rn.f32x2 %0,%1,%2,%0;" : "+l"(d) : "l"(a), "l"(b));
}
__device__ __forceinline__ void mul2(u64& d, u64 a) {
    asm("mul.rn.f32x2 %0,%0,%1;" : "+l"(d) : "l"(a));
}
__device__ __forceinline__ void upk(u64 v, float& lo, float& hi) {
    asm("mov.b64 {%0,%1},%2;" : "=f"(lo), "=f"(hi) : "l"(v));
}

// Scratch (static device allocations; no cudaMalloc allowed)
__device__ float g_q[BB * TT * HS];
__device__ float g_k[BB * TT * HS];
__device__ float g_v[BB * TT * HS];
__device__ float g_p2[3 * BB * TT * HS];    // K-split second-half partials
__device__ float g_pacc[(size_t)BB * KSPLIT * TT * HS];
__device__ float g_pm[BB * KSPLIT * TT];
__device__ float g_pl[BB * KSPLIT * TT];

// ---------------------------------------------------------------------------
// Kernel 1: QKV projection with K-split.
// X[8192,1024] @ W[1024,64] for Wq/Wk/Wv, K split in 2 halves of 512.
// grid = (128 row-tiles, 3 matrices, 2 k-halves), 256 threads.
// BM=64, BN=64, BK=32.  4x4 micro-tile, FFMA2 accumulators.
// Xs padded to stride 68 (kills 4-way STS conflict); register prefetch of
// the next chunk overlaps GMEM latency with the FMA loop.
// ---------------------------------------------------------------------------
__global__ __launch_bounds__(256) void qkv_kernel(
    const float* __restrict__ x,
    const float* __restrict__ Wq,
    const float* __restrict__ Wk,
    const float* __restrict__ Wv) {
    const int m = blockIdx.y;
    const float* W = (m == 0) ? Wq : (m == 1) ? Wk : Wv;
    float* out = (blockIdx.z == 0)
        ? ((m == 0) ? g_q : (m == 1) ? g_k : g_v)
        : &g_p2[(size_t)m * BB * TT * HS];

    __shared__ float Xs[32][68];   // [k][row], padded stride
    __shared__ float Ws[32][64];   // [k][col]

    const int tid = threadIdx.x;
    const int tx = tid & 15;       // 16 col groups of 4
    const int ty = tid >> 4;       // 16 row groups of 4
    const int row0 = blockIdx.x * 64;
    const int kbase = blockIdx.z * (CC / 2);

    const int lrow = tid >> 2;     // 0..63
    const int lq   = tid & 3;      // 0..3
    const int wk   = tid >> 3;     // 0..31
    const int wf   = tid & 7;      // 0..7

    u64 acc[4][2] = {};            // 4 rows x (2 f32x2 = 4 cols)

    // prefetch registers
    float4 px0, px1, pw0, pw1;

    // --- load chunk 0 to regs
    {
        const int k0 = kbase;
        px0 = *reinterpret_cast<const float4*>(
            &x[(size_t)(row0 + lrow) * CC + k0 + lq * 16]);
        px1 = *reinterpret_cast<const float4*>(
            &x[(size_t)(row0 + lrow) * CC + k0 + lq * 16 + 4 /*wrong slot? no:*/]);
        // slots: f = lq (first), f = lq+4 (second); each f covers 4 floats
        px1 = *reinterpret_cast<const float4*>(
            &x[(size_t)(row0 + lrow) * CC + k0 + (lq + 4) * 4]);
        px0 = *reinterpret_cast<const float4*>(
            &x[(size_t)(row0 + lrow) * CC + k0 + lq * 4]);
        pw0 = *reinterpret_cast<const float4*>(&W[(size_t)(k0 + wk) * HS + wf * 4]);
        pw1 = *reinterpret_cast<const float4*>(&W[(size_t)(k0 + wk) * HS + (wf + 8) * 4]);
    }

    for (int c = 0; c < 16; c++) {
        // store prefetched chunk to smem
        {
            int f0 = lq, f1 = lq + 4;
            Xs[f0 * 4 + 0][lrow] = px0.x;
            Xs[f0 * 4 + 1][lrow] = px0.y;
            Xs[f0 * 4 + 2][lrow] = px0.z;
            Xs[f0 * 4 + 3][lrow] = px0.w;
            Xs[f1 * 4 + 0][lrow] = px1.x;
            Xs[f1 * 4 + 1][lrow] = px1.y;
            Xs[f1 * 4 + 2][lrow] = px1.z;
            Xs[f1 * 4 + 3][lrow] = px1.w;
            *reinterpret_cast<float4*>(&Ws[wk][wf * 4]) = pw0;
            *reinterpret_cast<float4*>(&Ws[wk][(wf + 8) * 4]) = pw1;
        }
        __syncthreads();

        // issue gmem loads for next chunk (overlap with FMA below)
        if (c < 15) {
            const int k0 = kbase + (c + 1) * 32;
            px0 = *reinterpret_cast<const float4*>(
                &x[(size_t)(row0 + lrow) * CC + k0 + lq * 4]);
            px1 = *reinterpret_cast<const float4*>(
                &x[(size_t)(row0 + lrow) * CC + k0 + (lq + 4) * 4]);
            pw0 = *reinterpret_cast<const float4*>(
                &W[(size_t)(k0 + wk) * HS + wf * 4]);
            pw1 = *reinterpret_cast<const float4*>(
                &W[(size_t)(k0 + wk) * HS + (wf + 8) * 4]);
        }

#pragma unroll
        for (int kk = 0; kk < 32; kk++) {
            float4 a = *reinterpret_cast<float4*>(&Xs[kk][ty * 4]);
            float4 b = *reinterpret_cast<float4*>(&Ws[kk][tx * 4]);
            u64 b01 = pk2(b.x, b.y);
            u64 b23 = pk2(b.z, b.w);
            float av[4] = {a.x, a.y, a.z, a.w};
#pragma unroll
            for (int i = 0; i < 4; i++) {
                u64 ai = pk1(av[i]);
                fma2(acc[i][0], ai, b01);
                fma2(acc[i][1], ai, b23);
            }
        }
        __syncthreads();
    }

#pragma unroll
    for (int i = 0; i < 4; i++) {
        *reinterpret_cast<ulonglong2*>(
            &out[(size_t)(row0 + ty * 4 + i) * HS + tx * 4]) =
            make_ulonglong2(acc[i][0], acc[i][1]);
    }
}

// ---------------------------------------------------------------------------
// Kernel 1b: merge the two K-halves:  g_{q,k,v} += g_p2[m]
// ---------------------------------------------------------------------------
__global__ __launch_bounds__(256) void qkv_add_kernel() {
    const int f4 = blockIdx.x * 256 + threadIdx.x;   // f4 index, 3*524288/4 total
    const int per = (BB * TT * HS) / 4;              // 131072 f4 per matrix
    const int m = f4 / per;
    const int i = f4 - m * per;
    float* g = (m == 0) ? g_q : (m == 1) ? g_k : g_v;
    float4 a = *reinterpret_cast<float4*>(&g[i * 4]);
    float4 b = *reinterpret_cast<const float4*>(
        &g_p2[(size_t)m * BB * TT * HS + i * 4]);
    a.x += b.x; a.y += b.y; a.z += b.z; a.w += b.w;
    *reinterpret_cast<float4*>(&g[i * 4]) = a;
}

// ---------------------------------------------------------------------------
// Kernel 2: flash-attention partials with key-split (FFMA2) — unchanged R3.
// grid = (32 q-tiles, KSPLIT, 4 batches), 128 threads.  BM=BN=64.
// ---------------------------------------------------------------------------
__global__ __launch_bounds__(128) void attn_partial_kernel() {
    const int qtile = blockIdx.x;
    const int split = blockIdx.y;
    const int b     = blockIdx.z;

    const int tid = threadIdx.x;
    const int tx = tid & 15;
    const int ty = tid >> 4;

    __shared__ float Qt[64][64];
    __shared__ float KP[64][64];
    __shared__ float Vs[64][64];

    const int q0 = qtile * 64;
    const int lrow = tid >> 1;
    const int lh   = tid & 1;

#pragma unroll
    for (int i = 0; i < 8; i++) {
        int f = lh + 2 * i;
        float4 qv = *reinterpret_cast<const float4*>(
            &g_q[(size_t)(b * TT + q0 + lrow) * HS + f * 4]);
        Qt[f * 4 + 0][lrow] = qv.x * SCALE;
        Qt[f * 4 + 1][lrow] = qv.y * SCALE;
        Qt[f * 4 + 2][lrow] = qv.z * SCALE;
        Qt[f * 4 + 3][lrow] = qv.w * SCALE;
    }

    float m_[8], l_[8];
    u64 acc[8][2] = {};
#pragma unroll
    for (int i = 0; i < 8; i++) { m_[i] = -1e30f; l_[i] = 0.f; }

    for (int kt = split; kt <= qtile; kt += KSPLIT) {
        const int k0 = kt * 64;
        __syncthreads();

#pragma unroll
        for (int i = 0; i < 8; i++) {
            int f = lh + 2 * i;
            float4 kv = *reinterpret_cast<const float4*>(
                &g_k[(size_t)(b * TT + k0 + lrow) * HS + f * 4]);
            KP[f * 4 + 0][lrow] = kv.x;
            KP[f * 4 + 1][lrow] = kv.y;
            KP[f * 4 + 2][lrow] = kv.z;
            KP[f * 4 + 3][lrow] = kv.w;
            *reinterpret_cast<float4*>(&Vs[lrow][f * 4]) =
                *reinterpret_cast<const float4*>(
                    &g_v[(size_t)(b * TT + k0 + lrow) * HS + f * 4]);
        }
        __syncthreads();

        u64 sp[8][2] = {};
#pragma unroll 16
        for (int h = 0; h < 64; h++) {
            float4 a0 = *reinterpret_cast<float4*>(&Qt[h][ty * 8]);
            float4 a1 = *reinterpret_cast<float4*>(&Qt[h][ty * 8 + 4]);
            float4 bb = *reinterpret_cast<float4*>(&KP[h][tx * 4]);
            u64 b01 = pk2(bb.x, bb.y);
            u64 b23 = pk2(bb.z, bb.w);
            float av[8] = {a0.x, a0.y, a0.z, a0.w, a1.x, a1.y, a1.z, a1.w};
#pragma unroll
            for (int i = 0; i < 8; i++) {
                u64 ai = pk1(av[i]);
                fma2(sp[i][0], ai, b01);
                fma2(sp[i][1], ai, b23);
            }
        }

        float s[8][4];
#pragma unroll
        for (int i = 0; i < 8; i++) {
            upk(sp[i][0], s[i][0], s[i][1]);
            upk(sp[i][1], s[i][2], s[i][3]);
        }

        if (kt == qtile) {
#pragma unroll
            for (int i = 0; i < 8; i++)
#pragma unroll
                for (int j = 0; j < 4; j++)
                    if (tx * 4 + j > ty * 8 + i) s[i][j] = -1e30f;
        }

#pragma unroll
        for (int i = 0; i < 8; i++) {
            float tm = fmaxf(fmaxf(s[i][0], s[i][1]), fmaxf(s[i][2], s[i][3]));
#pragma unroll
            for (int o = 1; o < 16; o <<= 1)
                tm = fmaxf(tm, __shfl_xor_sync(0xffffffffu, tm, o));
            float nm  = fmaxf(m_[i], tm);
            float cor = __expf(m_[i] - nm);
            float rs = 0.f;
#pragma unroll
            for (int j = 0; j < 4; j++) {
                s[i][j] = __expf(s[i][j] - nm);
                rs += s[i][j];
            }
#pragma unroll
            for (int o = 1; o < 16; o <<= 1)
                rs += __shfl_xor_sync(0xffffffffu, rs, o);
            l_[i] = l_[i] * cor + rs;
            m_[i] = nm;
            u64 corp = pk1(cor);
            mul2(acc[i][0], corp);
            mul2(acc[i][1], corp);
        }

        __syncthreads();
#pragma unroll
        for (int i = 0; i < 8; i++) {
            *reinterpret_cast<float4*>(&KP[ty * 8 + i][tx * 4]) =
                make_float4(s[i][0], s[i][1], s[i][2], s[i][3]);
        }
        __syncthreads();

#pragma unroll
        for (int j4 = 0; j4 < 16; j4++) {
            float4 v0 = *reinterpret_cast<float4*>(&Vs[j4 * 4 + 0][tx * 4]);
            float4 v1 = *reinterpret_cast<float4*>(&Vs[j4 * 4 + 1][tx * 4]);
            float4 v2 = *reinterpret_cast<float4*>(&Vs[j4 * 4 + 2][tx * 4]);
            float4 v3 = *reinterpret_cast<float4*>(&Vs[j4 * 4 + 3][tx * 4]);
            u64 v0a = pk2(v0.x, v0.y), v0b = pk2(v0.z, v0.w);
            u64 v1a = pk2(v1.x, v1.y), v1b = pk2(v1.z, v1.w);
            u64 v2a = pk2(v2.x, v2.y), v2b = pk2(v2.z, v2.w);
            u64 v3a = pk2(v3.x, v3.y), v3b = pk2(v3.z, v3.w);
#pragma unroll
            for (int i = 0; i < 8; i++) {
                float4 p = *reinterpret_cast<float4*>(&KP[ty * 8 + i][j4 * 4]);
                u64 px = pk1(p.x), py = pk1(p.y), pz = pk1(p.z), pw = pk1(p.w);
                fma2(acc[i][0], px, v0a); fma2(acc[i][1], px, v0b);
                fma2(acc[i][0], py, v1a); fma2(acc[i][1], py, v1b);
                fma2(acc[i][0], pz, v2a); fma2(acc[i][1], pz, v2b);
                fma2(acc[i][0], pw, v3a); fma2(acc[i][1], pw, v3b);
            }
        }
    }

    const size_t base = (size_t)(b * KSPLIT + split) * TT + q0;
#pragma unroll
    for (int i = 0; i < 8; i++) {
        int r = ty * 8 + i;
        *reinterpret_cast<ulonglong2*>(&g_pacc[(base + r) * HS + tx * 4]) =
            make_ulonglong2(acc[i][0], acc[i][1]);
        if (tx == 0) {
            g_pm[base + r] = m_[i];
            g_pl[base + r] = l_[i];
        }
    }
}

// ---------------------------------------------------------------------------
// Kernel 3: combine split partials into the final output.
// ---------------------------------------------------------------------------
__global__ __launch_bounds__(256) void combine_kernel(float* __restrict__ out) {
    const int idx = blockIdx.x * 256 + threadIdx.x;
    const int d   = idx & (HS - 1);
    const int row = idx >> 6;
    const int b   = row >> 11;
    const int q   = row & (TT - 1);

    float M = -1e30f;
#pragma unroll
    for (int s = 0; s < KSPLIT; s++)
        M = fmaxf(M, g_pm[(size_t)(b * KSPLIT + s) * TT + q]);

    float L = 0.f, A = 0.f;
#pragma unroll
    for (int s = 0; s < KSPLIT; s++) {
        size_t pb = (size_t)(b * KSPLIT + s) * TT + q;
        float w = __expf(g_pm[pb] - M);
        L += g_pl[pb] * w;
        A += g_pacc[pb * HS + d] * w;
    }
    out[idx] = A / L;
}

// ---------------------------------------------------------------------------
extern "C" void kernel_launch(void* const* d_in, const int* in_sizes, int n_in,
                              void* d_out, int out_size) {
    const float* x  = (const float*)d_in[0];
    const float* Wq = (const float*)d_in[1];
    const float* Wk = (const float*)d_in[2];
    const float* Wv = (const float*)d_in[3];
    float* out = (float*)d_out;

    qkv_kernel<<<dim3((BB * TT) / 64, 3, 2), 256>>>(x, Wq, Wk, Wv);
    qkv_add_kernel<<<(3 * BB * TT * HS / 4) / 256, 256>>>();
    attn_partial_kernel<<<dim3(TT / 64, KSPLIT, BB), 128>>>();
    combine_kernel<<<(BB * TT * HS) / 256, 256>>>(out);
}